// round 16
// baseline (speedup 1.0000x reference)
#include <cuda_runtime.h>
#include <cuda_fp16.h>
#include <math.h>
#include <cstdint>

#define N_NODES  100000
#define N_EDGES  1600000
#define N_GRAPHS 2048
#define SCAN_BLOCKS ((N_NODES + 1023) / 1024)   // 98
#define MPAD 100096                              // 782 * 128

// Baug layout: W1 [256,96] @ 0 ; W2 [256,256] @ 24576 ; W3 [384,256] @ 90112
#define B1_OFF 0
#define B2_OFF 24576
#define B3_OFF 90112
#define B_TOTAL 188416

// ---------------- scratch (device globals: no allocation allowed) ----------
__device__ __half g_xh[(size_t)N_NODES * 80];              // x in fp16, padded
__device__ __half g_bufh[(size_t)N_NODES * 256];           // h1, h2 (fp16)
__device__ __half g_bufh3[(size_t)N_NODES * 384];          // h3 (fp16)
__device__ __half g_Aaug[(size_t)MPAD * 256];              // [MPAD, KS] fp16
__device__ __half g_Baug[B_TOTAL];                         // all weights fp16
__device__ int2  g_edge[N_EDGES];                          // (src, w-as-int)
__device__ int   g_deg[N_NODES];
__device__ int   g_rowstart[N_NODES + 1];
__device__ int   g_cursor[N_NODES];
__device__ float g_dinv[N_NODES];
__device__ int   g_bsums[128];

// ======================= low-level helpers ==================================
__device__ __forceinline__ uint32_t smem_u32(const void* p) {
    uint32_t a;
    asm("{ .reg .u64 t; cvta.to.shared.u64 t, %1; cvt.u32.u64 %0, t; }"
        : "=r"(a) : "l"(p));
    return a;
}

__device__ __forceinline__ void cp_async16(uint32_t dst, const void* src) {
    asm volatile("cp.async.cg.shared.global [%0], [%1], 16;"
                 :: "r"(dst), "l"(src));
}
__device__ __forceinline__ void cp_commit() {
    asm volatile("cp.async.commit_group;");
}
__device__ __forceinline__ void cp_wait1() {
    asm volatile("cp.async.wait_group 1;");
}
__device__ __forceinline__ void cp_wait0() {
    asm volatile("cp.async.wait_group 0;");
}

__device__ __forceinline__ void ldsm_x4(uint32_t& r0, uint32_t& r1,
                                        uint32_t& r2, uint32_t& r3, uint32_t addr) {
    asm volatile("ldmatrix.sync.aligned.m8n8.x4.shared.b16 {%0,%1,%2,%3}, [%4];"
                 : "=r"(r0), "=r"(r1), "=r"(r2), "=r"(r3) : "r"(addr));
}

__device__ __forceinline__ void mma16816(float* c, const uint32_t* a, const uint32_t* b) {
    asm volatile(
        "mma.sync.aligned.m16n8k16.row.col.f32.f16.f16.f32 "
        "{%0,%1,%2,%3}, {%4,%5,%6,%7}, {%8,%9}, {%0,%1,%2,%3};"
        : "+f"(c[0]), "+f"(c[1]), "+f"(c[2]), "+f"(c[3])
        : "r"(a[0]), "r"(a[1]), "r"(a[2]), "r"(a[3]), "r"(b[0]), "r"(b[1]));
}

__device__ __forceinline__ uint32_t pack_hf2(__half a, __half b) {
    __half2 t = __halves2half2(a, b);
    return *(uint32_t*)&t;
}

__device__ __forceinline__ float2 unpack_w(uint32_t w) {
    return __half22float2(*reinterpret_cast<const __half2*>(&w));
}

// ---------------- histogram: deg (edges only; deg zeroed by memset) ---------
__global__ void k_hist(const int* __restrict__ dst) {
    int i = blockIdx.x * blockDim.x + threadIdx.x;
    if (i < N_EDGES) atomicAdd(&g_deg[dst[i]], 1);
}

// ---------------- exclusive scan over deg: 2 kernels --------------------------
__global__ void k_scan_block(const int* __restrict__ in, int* __restrict__ out,
                             int n, int* __restrict__ bsums) {
    __shared__ int sm[1024];
    int i = blockIdx.x * 1024 + threadIdx.x;
    int v = (i < n) ? in[i] : 0;
    sm[threadIdx.x] = v;
    __syncthreads();
    for (int off = 1; off < 1024; off <<= 1) {
        int t = (threadIdx.x >= off) ? sm[threadIdx.x - off] : 0;
        __syncthreads();
        sm[threadIdx.x] += t;
        __syncthreads();
    }
    if (i < n) out[i] = sm[threadIdx.x] - v;           // exclusive
    if (threadIdx.x == 1023) bsums[blockIdx.x] = sm[1023];
}

// scans bsums in-kernel (smem), adds block offset; also cursor copy + dinv
__global__ void k_scan_add(int* __restrict__ out, int n,
                           const int* __restrict__ bsums, int total,
                           int* __restrict__ cursor) {
    __shared__ int sb[128];
    int t = threadIdx.x;
    if (t < 128) sb[t] = (t < SCAN_BLOCKS) ? bsums[t] : 0;
    __syncthreads();
    for (int off = 1; off < 128; off <<= 1) {
        int v = 0;
        if (t < 128 && t >= off) v = sb[t - off];
        __syncthreads();
        if (t < 128) sb[t] += v;
        __syncthreads();
    }
    int boff = (blockIdx.x == 0) ? 0 : sb[blockIdx.x - 1];   // exclusive prefix
    int i = blockIdx.x * 1024 + t;
    if (i < n) {
        int v = out[i] + boff;
        out[i] = v;
        cursor[i] = v;
        g_dinv[i] = rsqrtf((float)g_deg[i] + 1.0f);
    }
    if (i == 0) out[n] = total;
}

// ---------------- CSR fill (w precomputed) + x->fp16 conversion, fused -------
__global__ void k_fill_convX(const int* __restrict__ src, const int* __restrict__ dst,
                             const float* __restrict__ x, __half* __restrict__ xh) {
    int idx = blockIdx.x * blockDim.x + threadIdx.x;
    if (idx < N_EDGES) {
        int s = src[idx], d = dst[idx];
        int p = atomicAdd(&g_cursor[d], 1);
        float w = g_dinv[s] * g_dinv[d];
        int2 pr;
        pr.x = s;
        pr.y = __float_as_int(w);
        g_edge[p] = pr;
    }
    if (idx < N_NODES * 80) {
        int r = idx / 80, c = idx % 80;
        xh[idx] = __float2half_rn((c < 74) ? x[r * 74 + c] : 0.0f);
    }
}

// ---------------- all weights fp32 -> fp16 transposed, one launch ------------
__global__ void k_convB_all(const float* __restrict__ W1,
                            const float* __restrict__ W2,
                            const float* __restrict__ W3,
                            __half* __restrict__ B) {
    int idx = blockIdx.x * blockDim.x + threadIdx.x;
    if (idx >= B_TOTAL) return;
    float v;
    if (idx < B2_OFF) {                    // W1: [74,256] -> [256,96]
        int r = idx;
        int n = r / 96, k = r % 96;
        v = (k < 74) ? W1[k * 256 + n] : 0.0f;
    } else if (idx < B3_OFF) {             // W2: [256,256] -> [256,256]
        int r = idx - B2_OFF;
        int n = r / 256, k = r % 256;
        v = W2[k * 256 + n];
    } else {                               // W3: [256,384] -> [384,256]
        int r = idx - B3_OFF;
        int n = r / 256, k = r % 256;
        v = W3[k * 384 + n];
    }
    B[idx] = __float2half_rn(v);
}

// edge loader with exact-zero padding: j >= re -> (self, w=0); 0*row == 0
__device__ __forceinline__ int2 load_edge(int j, int re, int self) {
    if (j < re) return g_edge[j];
    int2 p; p.x = self; p.y = 0; return p;   // 0 bits == 0.0f
}

// ---------------- layer-1 aggregate: xh [N,80] fp16 -> Aaug [N,96] fp16 -----
// Depth-2 software pipeline (R14 shape).
__global__ void k_agg_pre74h(const __half* __restrict__ xh,
                             __half* __restrict__ Aaug) {
    int gw = (int)((blockIdx.x * blockDim.x + threadIdx.x) >> 5);
    if (gw >= N_NODES) return;
    int lane = threadIdx.x & 31;
    int rs = g_rowstart[gw], re = g_rowstart[gw + 1];
    float di = g_dinv[gw];
    float self = di * di;
    bool act = lane < 20;
    float acc[4] = {0.f, 0.f, 0.f, 0.f};
    if (act) {
        uint2 t = *(const uint2*)(xh + (size_t)gw * 80 + lane * 4);
        float2 f0 = unpack_w(t.x), f1 = unpack_w(t.y);
        acc[0] = f0.x * self; acc[1] = f0.y * self;
        acc[2] = f1.x * self; acc[3] = f1.y * self;
    }
    int2 c0 = load_edge(rs, re, gw);
    int2 c1 = load_edge(rs + 1, re, gw);
    for (int e = rs; e < re; e += 2) {
        uint2 t0 = make_uint2(0u, 0u), t1 = make_uint2(0u, 0u);
        if (act) {
            t0 = *(const uint2*)(xh + (size_t)c0.x * 80 + lane * 4);
            t1 = *(const uint2*)(xh + (size_t)c1.x * 80 + lane * 4);
        }
        float w0 = __int_as_float(c0.y);
        float w1 = __int_as_float(c1.y);
        c0 = load_edge(e + 2, re, gw);        // prefetch next pair
        c1 = load_edge(e + 3, re, gw);
        if (act) {
            float2 a0 = unpack_w(t0.x), a1 = unpack_w(t0.y);
            float2 b0 = unpack_w(t1.x), b1 = unpack_w(t1.y);
            acc[0] += a0.x * w0 + b0.x * w1;
            acc[1] += a0.y * w0 + b0.y * w1;
            acc[2] += a1.x * w0 + b1.x * w1;
            acc[3] += a1.y * w0 + b1.y * w1;
        }
    }
    size_t base = (size_t)gw * 96;
    if (act) {
        uint2 o;
        o.x = pack_hf2(__float2half_rn(acc[0]), __float2half_rn(acc[1]));
        o.y = pack_hf2(__float2half_rn(acc[2]), __float2half_rn(acc[3]));
        *(uint2*)(Aaug + base + lane * 4) = o;
    } else if (lane < 24) {
        *(uint2*)(Aaug + base + lane * 4) = make_uint2(0u, 0u);
    }
}

// ---------------- aggregate (F=256, fp16 in): TWO warps per node -------------
// Warp owns 128 columns (uint2 = 4 halves per lane). Doubles warp-level
// parallelism to hide the edge->row latency chain.
__global__ void k_agg_pre256h(const __half* __restrict__ hin,
                              __half* __restrict__ Aaug) {
    int gw2 = (int)((blockIdx.x * blockDim.x + threadIdx.x) >> 5);
    int gw = gw2 >> 1;                 // node
    if (gw >= N_NODES) return;
    int half = gw2 & 1;                // which 128-column half
    int lane = threadIdx.x & 31;
    int coff = half * 128 + lane * 4;  // column offset (halves)
    int rs = g_rowstart[gw], re = g_rowstart[gw + 1];
    float di = g_dinv[gw];
    float self = di * di;
    float acc[4];
    {
        uint2 t = *(const uint2*)(hin + (size_t)gw * 256 + coff);
        float2 f0 = unpack_w(t.x), f1 = unpack_w(t.y);
        acc[0] = f0.x * self; acc[1] = f0.y * self;
        acc[2] = f1.x * self; acc[3] = f1.y * self;
    }
    int2 c0 = load_edge(rs, re, gw);
    int2 c1 = load_edge(rs + 1, re, gw);
    for (int e = rs; e < re; e += 2) {
        uint2 t0 = *(const uint2*)(hin + (size_t)c0.x * 256 + coff);
        uint2 t1 = *(const uint2*)(hin + (size_t)c1.x * 256 + coff);
        float w0 = __int_as_float(c0.y);
        float w1 = __int_as_float(c1.y);
        c0 = load_edge(e + 2, re, gw);        // prefetch next pair
        c1 = load_edge(e + 3, re, gw);
        float2 a0 = unpack_w(t0.x), a1 = unpack_w(t0.y);
        float2 b0 = unpack_w(t1.x), b1 = unpack_w(t1.y);
        acc[0] += a0.x * w0 + b0.x * w1;
        acc[1] += a0.y * w0 + b0.y * w1;
        acc[2] += a1.x * w0 + b1.x * w1;
        acc[3] += a1.y * w0 + b1.y * w1;
    }
    uint2 o;
    o.x = pack_hf2(__float2half_rn(acc[0]), __float2half_rn(acc[1]));
    o.y = pack_hf2(__float2half_rn(acc[2]), __float2half_rn(acc[3]));
    *(uint2*)(Aaug + (size_t)gw * 256 + coff) = o;
}

// ---------------- fp16 mma.sync GEMM + fused epilogue ------------------------
#define GS 40   // smem row stride in halves (32 data + 8 pad = 80B, conflict-free)

template <int EPI>
__global__ __launch_bounds__(256, 2)
void k_gemm_mma(const __half* __restrict__ A,
                const __half* __restrict__ B,
                __half* __restrict__ Ch,
                int K, int NTOT,
                const float* __restrict__ bias,
                const float* __restrict__ gamma,
                const float* __restrict__ beta,
                const float* __restrict__ rm,
                const float* __restrict__ rv) {
    __shared__ __align__(16) __half As[2][128 * GS];
    __shared__ __align__(16) __half Bs[2][128 * GS];

    int tid = threadIdx.x;
    int wid = tid >> 5, lane = tid & 31;
    int warp_m = wid & 1;
    int warp_n = wid >> 1;
    int rowBase = blockIdx.y * 128;
    int colBase = blockIdx.x * 128;

    uint32_t asb = smem_u32(&As[0][0]);
    uint32_t bsb = smem_u32(&Bs[0][0]);
    const uint32_t bufBytes = 128 * GS * 2;

    float acc[4][4][4];
#pragma unroll
    for (int i = 0; i < 4; i++)
#pragma unroll
        for (int j = 0; j < 4; j++)
#pragma unroll
            for (int q = 0; q < 4; q++) acc[i][j][q] = 0.0f;

    const int NC = K >> 5;

    auto load_chunk = [&](int c, int buf) {
        int k0 = c << 5;
#pragma unroll
        for (int t = 0; t < 2; t++) {
            int idx = tid + (t << 8);
            int r = idx >> 2, seg = idx & 3;
            uint32_t doff = (uint32_t)(r * GS + seg * 8) * 2;
            cp_async16(asb + buf * bufBytes + doff,
                       A + (size_t)(rowBase + r) * K + k0 + seg * 8);
            cp_async16(bsb + buf * bufBytes + doff,
                       B + (size_t)(colBase + r) * K + k0 + seg * 8);
        }
        cp_commit();
    };

    load_chunk(0, 0);

    for (int c = 0; c < NC; c++) {
        int buf = c & 1;
        if (c + 1 < NC) {
            load_chunk(c + 1, buf ^ 1);
            cp_wait1();
        } else {
            cp_wait0();
        }
        __syncthreads();

        uint32_t aBase = asb + buf * bufBytes;
        uint32_t bBase = bsb + buf * bufBytes;
#pragma unroll
        for (int kk = 0; kk < 2; kk++) {
            uint32_t af[4][4];
            {
                int row = warp_m * 64 + (lane & 15);
                int kcol = kk * 16 + ((lane >> 4) << 3);
#pragma unroll
                for (int i = 0; i < 4; i++) {
                    uint32_t addr = aBase + (uint32_t)((row + i * 16) * GS + kcol) * 2;
                    ldsm_x4(af[i][0], af[i][1], af[i][2], af[i][3], addr);
                }
            }
            uint32_t bf[4][2];
            {
                int rown = warp_n * 32 + (lane & 7) + ((lane & 16) ? 8 : 0);
                int kcol = kk * 16 + ((lane & 8) ? 8 : 0);
#pragma unroll
                for (int jj = 0; jj < 2; jj++) {
                    uint32_t addr = bBase + (uint32_t)((rown + jj * 16) * GS + kcol) * 2;
                    ldsm_x4(bf[jj * 2][0], bf[jj * 2][1],
                            bf[jj * 2 + 1][0], bf[jj * 2 + 1][1], addr);
                }
            }
#pragma unroll
            for (int i = 0; i < 4; i++)
#pragma unroll
                for (int j = 0; j < 4; j++)
                    mma16816(acc[i][j], af[i], bf[j]);
        }
        __syncthreads();
    }

    int mrow0 = rowBase + warp_m * 64 + (lane >> 2);
    int ncol0 = colBase + warp_n * 32 + ((lane & 3) << 1);
#pragma unroll
    for (int j = 0; j < 4; j++) {
        int n = ncol0 + j * 8;
        float b0 = bias[n], b1 = bias[n + 1];
        float s0 = 0.f, s1 = 0.f, t0 = 0.f, t1 = 0.f, m0 = 0.f, m1 = 0.f;
        if (EPI) {
            s0 = gamma[n]     * rsqrtf(rv[n]     + 1e-5f);
            s1 = gamma[n + 1] * rsqrtf(rv[n + 1] + 1e-5f);
            t0 = beta[n];  t1 = beta[n + 1];
            m0 = rm[n];    m1 = rm[n + 1];
        }
#pragma unroll
        for (int i = 0; i < 4; i++) {
            int m_a = mrow0 + i * 16;
            int m_b = m_a + 8;
            float v0 = acc[i][j][0] + b0, v1 = acc[i][j][1] + b1;
            float v2 = acc[i][j][2] + b0, v3 = acc[i][j][3] + b1;
            if (EPI) {
                v0 = fmaxf((v0 - m0) * s0 + t0, 0.0f);
                v1 = fmaxf((v1 - m1) * s1 + t1, 0.0f);
                v2 = fmaxf((v2 - m0) * s0 + t0, 0.0f);
                v3 = fmaxf((v3 - m1) * s1 + t1, 0.0f);
            }
            if (m_a < N_NODES) {
                uint32_t p = pack_hf2(__float2half_rn(v0), __float2half_rn(v1));
                *(uint32_t*)(Ch + (size_t)m_a * NTOT + n) = p;
            }
            if (m_b < N_NODES) {
                uint32_t p = pack_hf2(__float2half_rn(v2), __float2half_rn(v3));
                *(uint32_t*)(Ch + (size_t)m_b * NTOT + n) = p;
            }
        }
    }
}

// ---------------- pooling: mean + max per graph; segment via binary search --
__global__ void k_pool(const __half* __restrict__ h3,
                       const int* __restrict__ batch,
                       float* __restrict__ out) {
    int g = blockIdx.x;
    int tx = threadIdx.x;
    int lo = 0, hi = N_NODES;
    while (lo < hi) { int mid = (lo + hi) >> 1; if (batch[mid] < g) lo = mid + 1; else hi = mid; }
    int s = lo;
    lo = s; hi = N_NODES;
    while (lo < hi) { int mid = (lo + hi) >> 1; if (batch[mid] < g + 1) lo = mid + 1; else hi = mid; }
    int e = lo;

    float sum[3] = {0.f, 0.f, 0.f};
    float mx[3]  = {-INFINITY, -INFINITY, -INFINITY};
    for (int n = s; n < e; n++) {
#pragma unroll
        for (int c = 0; c < 3; c++) {
            float v = __half2float(h3[(size_t)n * 384 + tx + c * 128]);
            sum[c] += v;
            mx[c] = fmaxf(mx[c], v);
        }
    }
    float inv = 1.0f / fmaxf((float)(e - s), 1.0f);
#pragma unroll
    for (int c = 0; c < 3; c++)
        out[(size_t)g * 384 + tx + c * 128] = sum[c] * inv + mx[c];
}

// ---------------- launch ----------------------------------------------------
extern "C" void kernel_launch(void* const* d_in, const int* in_sizes, int n_in,
                              void* d_out, int out_size) {
    const float* x     = (const float*)d_in[0];
    const int*   ei    = (const int*)d_in[1];   // [2, E] int32
    const int*   src   = ei;
    const int*   dst   = ei + N_EDGES;
    const int*   batch = (const int*)d_in[2];
    const float* W1 = (const float*)d_in[3];
    const float* b1 = (const float*)d_in[4];
    const float* g1 = (const float*)d_in[5];
    const float* be1 = (const float*)d_in[6];
    const float* rm1 = (const float*)d_in[7];
    const float* rv1 = (const float*)d_in[8];
    const float* W2 = (const float*)d_in[9];
    const float* b2 = (const float*)d_in[10];
    const float* g2 = (const float*)d_in[11];
    const float* be2 = (const float*)d_in[12];
    const float* rm2 = (const float*)d_in[13];
    const float* rv2 = (const float*)d_in[14];
    const float* W3 = (const float*)d_in[15];
    const float* b3 = (const float*)d_in[16];
    float* out = (float*)d_out;

    __half *p_xh, *p_bufh, *p_bufh3, *p_Aaug, *p_Baug;
    int *p_deg, *p_rowstart, *p_cursor, *p_bsums;
    cudaGetSymbolAddress((void**)&p_xh, g_xh);
    cudaGetSymbolAddress((void**)&p_bufh, g_bufh);
    cudaGetSymbolAddress((void**)&p_bufh3, g_bufh3);
    cudaGetSymbolAddress((void**)&p_Aaug, g_Aaug);
    cudaGetSymbolAddress((void**)&p_Baug, g_Baug);
    cudaGetSymbolAddress((void**)&p_deg, g_deg);
    cudaGetSymbolAddress((void**)&p_rowstart, g_rowstart);
    cudaGetSymbolAddress((void**)&p_cursor, g_cursor);
    cudaGetSymbolAddress((void**)&p_bsums, g_bsums);

    const int AGG_BLOCKS  = (N_NODES + 7) / 8;       // 1 warp/node kernels
    const int AGG_BLOCKS2 = (N_NODES * 2 + 7) / 8;   // 2 warps/node kernel

    // zeroing via memset node (not counted as kernel launch)
    cudaMemsetAsync(p_deg, 0, N_NODES * sizeof(int));

    // ---- 1..4: CSR construction + x conversion ----
    k_hist<<<(N_EDGES + 255) / 256, 256>>>(dst);
    k_scan_block<<<SCAN_BLOCKS, 1024>>>(p_deg, p_rowstart, N_NODES, p_bsums);
    k_scan_add<<<SCAN_BLOCKS, 1024>>>(p_rowstart, N_NODES, p_bsums,
                                      N_EDGES, p_cursor);
    k_fill_convX<<<(N_NODES * 80 + 255) / 256, 256>>>(src, dst, x, p_xh);

    // ---- 5: layer-1 aggregate ----
    k_agg_pre74h<<<AGG_BLOCKS, 256>>>(p_xh, p_Aaug);
    // ---- 6: all weights -> fp16 ----
    k_convB_all<<<(B_TOTAL + 255) / 256, 256>>>(W1, W2, W3, p_Baug);

    // ---- Layer 1: GEMM K=96 + BN+ReLU -> fp16 h1 ----
    {
        dim3 grid(256 / 128, MPAD / 128);
        k_gemm_mma<1><<<grid, 256>>>(p_Aaug, p_Baug + B1_OFF, p_bufh, 96, 256,
                                     b1, g1, be1, rm1, rv1);
    }
    // ---- Layer 2 ----
    {
        k_agg_pre256h<<<AGG_BLOCKS2, 256>>>(p_bufh, p_Aaug);
        dim3 grid(256 / 128, MPAD / 128);
        k_gemm_mma<1><<<grid, 256>>>(p_Aaug, p_Baug + B2_OFF, p_bufh, 256, 256,
                                     b2, g2, be2, rm2, rv2);
    }
    // ---- Layer 3 -> fp16 h3 ----
    {
        k_agg_pre256h<<<AGG_BLOCKS2, 256>>>(p_bufh, p_Aaug);
        dim3 grid(384 / 128, MPAD / 128);
        k_gemm_mma<0><<<grid, 256>>>(p_Aaug, p_Baug + B3_OFF, p_bufh3, 256, 384,
                                     b3, (const float*)0, (const float*)0,
                                     (const float*)0, (const float*)0);
    }
    // ---- pooling (segments via binary search on sorted batch) ----
    k_pool<<<N_GRAPHS, 128>>>(p_bufh3, batch, out);
}

// round 17
// speedup vs baseline: 1.1735x; 1.1735x over previous
#include <cuda_runtime.h>
#include <cuda_fp16.h>
#include <math.h>
#include <cstdint>

#define N_NODES  100000
#define N_EDGES  1600000
#define N_GRAPHS 2048
#define SCAN_BLOCKS ((N_NODES + 1023) / 1024)   // 98
#define MPAD 100096                              // 782 * 128

// Baug layout: W1 [256,96] @ 0 ; W2 [256,256] @ 24576 ; W3 [384,256] @ 90112
#define B1_OFF 0
#define B2_OFF 24576
#define B3_OFF 90112
#define B_TOTAL 188416

// ---------------- scratch (device globals: no allocation allowed) ----------
__device__ __half g_xh[(size_t)N_NODES * 80];              // x in fp16, padded
__device__ __half g_bufh[(size_t)N_NODES * 256];           // h1, h2 (fp16)
__device__ __half g_bufh3[(size_t)N_NODES * 384];          // h3 (fp16)
__device__ __half g_Aaug[(size_t)MPAD * 256];              // [MPAD, KS] fp16
__device__ __half g_Baug[B_TOTAL];                         // all weights fp16
__device__ __align__(16) int2 g_edge[N_EDGES];             // (src, w-as-int)
__device__ int   g_deg[N_NODES];
__device__ int   g_rowstart[N_NODES + 1];
__device__ int   g_cursor[N_NODES];
__device__ float g_dinv[N_NODES];
__device__ int   g_bsums[128];

// ======================= low-level helpers ==================================
__device__ __forceinline__ uint32_t smem_u32(const void* p) {
    uint32_t a;
    asm("{ .reg .u64 t; cvta.to.shared.u64 t, %1; cvt.u32.u64 %0, t; }"
        : "=r"(a) : "l"(p));
    return a;
}

__device__ __forceinline__ void cp_async16(uint32_t dst, const void* src) {
    asm volatile("cp.async.cg.shared.global [%0], [%1], 16;"
                 :: "r"(dst), "l"(src));
}
__device__ __forceinline__ void cp_commit() {
    asm volatile("cp.async.commit_group;");
}
__device__ __forceinline__ void cp_wait1() {
    asm volatile("cp.async.wait_group 1;");
}
__device__ __forceinline__ void cp_wait0() {
    asm volatile("cp.async.wait_group 0;");
}

__device__ __forceinline__ void ldsm_x4(uint32_t& r0, uint32_t& r1,
                                        uint32_t& r2, uint32_t& r3, uint32_t addr) {
    asm volatile("ldmatrix.sync.aligned.m8n8.x4.shared.b16 {%0,%1,%2,%3}, [%4];"
                 : "=r"(r0), "=r"(r1), "=r"(r2), "=r"(r3) : "r"(addr));
}

__device__ __forceinline__ void mma16816(float* c, const uint32_t* a, const uint32_t* b) {
    asm volatile(
        "mma.sync.aligned.m16n8k16.row.col.f32.f16.f16.f32 "
        "{%0,%1,%2,%3}, {%4,%5,%6,%7}, {%8,%9}, {%0,%1,%2,%3};"
        : "+f"(c[0]), "+f"(c[1]), "+f"(c[2]), "+f"(c[3])
        : "r"(a[0]), "r"(a[1]), "r"(a[2]), "r"(a[3]), "r"(b[0]), "r"(b[1]));
}

__device__ __forceinline__ uint32_t pack_hf2(__half a, __half b) {
    __half2 t = __halves2half2(a, b);
    return *(uint32_t*)&t;
}

__device__ __forceinline__ float2 unpack_w(uint32_t w) {
    return __half22float2(*reinterpret_cast<const __half2*>(&w));
}

// ---------------- histogram: deg (edges only; deg zeroed by memset) ---------
__global__ void k_hist(const int* __restrict__ dst) {
    int i = blockIdx.x * blockDim.x + threadIdx.x;
    if (i < N_EDGES) atomicAdd(&g_deg[dst[i]], 1);
}

// ---------------- exclusive scan over deg: 2 kernels --------------------------
__global__ void k_scan_block(const int* __restrict__ in, int* __restrict__ out,
                             int n, int* __restrict__ bsums) {
    __shared__ int sm[1024];
    int i = blockIdx.x * 1024 + threadIdx.x;
    int v = (i < n) ? in[i] : 0;
    sm[threadIdx.x] = v;
    __syncthreads();
    for (int off = 1; off < 1024; off <<= 1) {
        int t = (threadIdx.x >= off) ? sm[threadIdx.x - off] : 0;
        __syncthreads();
        sm[threadIdx.x] += t;
        __syncthreads();
    }
    if (i < n) out[i] = sm[threadIdx.x] - v;           // exclusive
    if (threadIdx.x == 1023) bsums[blockIdx.x] = sm[1023];
}

// scans bsums in-kernel (smem), adds block offset; also cursor copy + dinv
__global__ void k_scan_add(int* __restrict__ out, int n,
                           const int* __restrict__ bsums, int total,
                           int* __restrict__ cursor) {
    __shared__ int sb[128];
    int t = threadIdx.x;
    if (t < 128) sb[t] = (t < SCAN_BLOCKS) ? bsums[t] : 0;
    __syncthreads();
    for (int off = 1; off < 128; off <<= 1) {
        int v = 0;
        if (t < 128 && t >= off) v = sb[t - off];
        __syncthreads();
        if (t < 128) sb[t] += v;
        __syncthreads();
    }
    int boff = (blockIdx.x == 0) ? 0 : sb[blockIdx.x - 1];   // exclusive prefix
    int i = blockIdx.x * 1024 + t;
    if (i < n) {
        int v = out[i] + boff;
        out[i] = v;
        cursor[i] = v;
        g_dinv[i] = rsqrtf((float)g_deg[i] + 1.0f);
    }
    if (i == 0) out[n] = total;
}

// ---------------- CSR fill (w precomputed) + x->fp16 conversion, fused -------
__global__ void k_fill_convX(const int* __restrict__ src, const int* __restrict__ dst,
                             const float* __restrict__ x, __half* __restrict__ xh) {
    int idx = blockIdx.x * blockDim.x + threadIdx.x;
    if (idx < N_EDGES) {
        int s = src[idx], d = dst[idx];
        int p = atomicAdd(&g_cursor[d], 1);
        float w = g_dinv[s] * g_dinv[d];
        int2 pr;
        pr.x = s;
        pr.y = __float_as_int(w);
        g_edge[p] = pr;
    }
    if (idx < N_NODES * 80) {
        int r = idx / 80, c = idx % 80;
        xh[idx] = __float2half_rn((c < 74) ? x[r * 74 + c] : 0.0f);
    }
}

// ---------------- all weights fp32 -> fp16 transposed, one launch ------------
__global__ void k_convB_all(const float* __restrict__ W1,
                            const float* __restrict__ W2,
                            const float* __restrict__ W3,
                            __half* __restrict__ B) {
    int idx = blockIdx.x * blockDim.x + threadIdx.x;
    if (idx >= B_TOTAL) return;
    float v;
    if (idx < B2_OFF) {                    // W1: [74,256] -> [256,96]
        int r = idx;
        int n = r / 96, k = r % 96;
        v = (k < 74) ? W1[k * 256 + n] : 0.0f;
    } else if (idx < B3_OFF) {             // W2: [256,256] -> [256,256]
        int r = idx - B2_OFF;
        int n = r / 256, k = r % 256;
        v = W2[k * 256 + n];
    } else {                               // W3: [256,384] -> [384,256]
        int r = idx - B3_OFF;
        int n = r / 256, k = r % 256;
        v = W3[k * 384 + n];
    }
    B[idx] = __float2half_rn(v);
}

// ---------------- layer-1 aggregate: xh [N,80] fp16 -> Aaug [N,96] fp16 -----
// Paired edges: ONE aligned int4 broadcast covers TWO edge records.
__global__ void k_agg_pre74h(const __half* __restrict__ xh,
                             __half* __restrict__ Aaug) {
    int gw = (int)((blockIdx.x * blockDim.x + threadIdx.x) >> 5);
    if (gw >= N_NODES) return;
    int lane = threadIdx.x & 31;
    int rs = g_rowstart[gw], re = g_rowstart[gw + 1];
    float di = g_dinv[gw];
    float self = di * di;
    bool act = lane < 20;
    float acc[4] = {0.f, 0.f, 0.f, 0.f};
    if (act) {
        uint2 t = *(const uint2*)(xh + (size_t)gw * 80 + lane * 4);
        float2 f0 = unpack_w(t.x), f1 = unpack_w(t.y);
        acc[0] = f0.x * self; acc[1] = f0.y * self;
        acc[2] = f1.x * self; acc[3] = f1.y * self;
    }
    int e = rs;
    if ((e & 1) && e < re) {               // peel odd head
        int2 p = g_edge[e];
        float w0 = __int_as_float(p.y);
        if (act) {
            uint2 t0 = *(const uint2*)(xh + (size_t)p.x * 80 + lane * 4);
            float2 a0 = unpack_w(t0.x), a1 = unpack_w(t0.y);
            acc[0] += a0.x * w0; acc[1] += a0.y * w0;
            acc[2] += a1.x * w0; acc[3] += a1.y * w0;
        }
        e++;
    }
    for (; e + 2 <= re; e += 2) {          // e even: 16B-aligned pair load
        int4 pp = *(const int4*)(g_edge + e);
        float w0 = __int_as_float(pp.y);
        float w1 = __int_as_float(pp.w);
        if (act) {
            uint2 t0 = *(const uint2*)(xh + (size_t)pp.x * 80 + lane * 4);
            uint2 t1 = *(const uint2*)(xh + (size_t)pp.z * 80 + lane * 4);
            float2 a0 = unpack_w(t0.x), a1 = unpack_w(t0.y);
            float2 b0 = unpack_w(t1.x), b1 = unpack_w(t1.y);
            acc[0] += a0.x * w0 + b0.x * w1;
            acc[1] += a0.y * w0 + b0.y * w1;
            acc[2] += a1.x * w0 + b1.x * w1;
            acc[3] += a1.y * w0 + b1.y * w1;
        }
    }
    if (e < re) {                          // tail
        int2 p = g_edge[e];
        float w0 = __int_as_float(p.y);
        if (act) {
            uint2 t0 = *(const uint2*)(xh + (size_t)p.x * 80 + lane * 4);
            float2 a0 = unpack_w(t0.x), a1 = unpack_w(t0.y);
            acc[0] += a0.x * w0; acc[1] += a0.y * w0;
            acc[2] += a1.x * w0; acc[3] += a1.y * w0;
        }
    }
    size_t base = (size_t)gw * 96;
    if (act) {
        uint2 o;
        o.x = pack_hf2(__float2half_rn(acc[0]), __float2half_rn(acc[1]));
        o.y = pack_hf2(__float2half_rn(acc[2]), __float2half_rn(acc[3]));
        *(uint2*)(Aaug + base + lane * 4) = o;
    } else if (lane < 24) {
        *(uint2*)(Aaug + base + lane * 4) = make_uint2(0u, 0u);
    }
}

// ---------------- aggregate (F=256, fp16 in): one warp per node --------------
// Paired edges via aligned int4 broadcast; direct row loads (best-measured).
__global__ void k_agg_pre256h(const __half* __restrict__ hin,
                              __half* __restrict__ Aaug) {
    int gw = (int)((blockIdx.x * blockDim.x + threadIdx.x) >> 5);
    if (gw >= N_NODES) return;
    int lane = threadIdx.x & 31;
    int rs = g_rowstart[gw], re = g_rowstart[gw + 1];
    float di = g_dinv[gw];
    float self = di * di;
    float acc[8];
    {
        uint4 t = *(const uint4*)(hin + (size_t)gw * 256 + lane * 8);
        float2 f0 = unpack_w(t.x), f1 = unpack_w(t.y);
        float2 f2 = unpack_w(t.z), f3 = unpack_w(t.w);
        acc[0] = f0.x * self; acc[1] = f0.y * self;
        acc[2] = f1.x * self; acc[3] = f1.y * self;
        acc[4] = f2.x * self; acc[5] = f2.y * self;
        acc[6] = f3.x * self; acc[7] = f3.y * self;
    }
    auto add_one = [&](int s, float w) {
        uint4 t0 = *(const uint4*)(hin + (size_t)s * 256 + lane * 8);
        float2 a0 = unpack_w(t0.x), a1 = unpack_w(t0.y);
        float2 a2 = unpack_w(t0.z), a3 = unpack_w(t0.w);
        acc[0] += a0.x * w; acc[1] += a0.y * w;
        acc[2] += a1.x * w; acc[3] += a1.y * w;
        acc[4] += a2.x * w; acc[5] += a2.y * w;
        acc[6] += a3.x * w; acc[7] += a3.y * w;
    };
    int e = rs;
    if ((e & 1) && e < re) {               // peel odd head
        int2 p = g_edge[e];
        add_one(p.x, __int_as_float(p.y));
        e++;
    }
    for (; e + 2 <= re; e += 2) {          // e even: 16B-aligned pair load
        int4 pp = *(const int4*)(g_edge + e);
        float w0 = __int_as_float(pp.y);
        float w1 = __int_as_float(pp.w);
        uint4 t0 = *(const uint4*)(hin + (size_t)pp.x * 256 + lane * 8);
        uint4 t1 = *(const uint4*)(hin + (size_t)pp.z * 256 + lane * 8);
        float2 a0 = unpack_w(t0.x), a1 = unpack_w(t0.y);
        float2 a2 = unpack_w(t0.z), a3 = unpack_w(t0.w);
        float2 b0 = unpack_w(t1.x), b1 = unpack_w(t1.y);
        float2 b2 = unpack_w(t1.z), b3 = unpack_w(t1.w);
        acc[0] += a0.x * w0 + b0.x * w1;
        acc[1] += a0.y * w0 + b0.y * w1;
        acc[2] += a1.x * w0 + b1.x * w1;
        acc[3] += a1.y * w0 + b1.y * w1;
        acc[4] += a2.x * w0 + b2.x * w1;
        acc[5] += a2.y * w0 + b2.y * w1;
        acc[6] += a3.x * w0 + b3.x * w1;
        acc[7] += a3.y * w0 + b3.y * w1;
    }
    if (e < re) {                          // tail
        int2 p = g_edge[e];
        add_one(p.x, __int_as_float(p.y));
    }
    uint32_t hpk[4];
#pragma unroll
    for (int q = 0; q < 4; q++)
        hpk[q] = pack_hf2(__float2half_rn(acc[2 * q]), __float2half_rn(acc[2 * q + 1]));
    size_t obase = (size_t)gw * 256 + lane * 8;   // 16B-aligned
    *(uint4*)(Aaug + obase) = make_uint4(hpk[0], hpk[1], hpk[2], hpk[3]);
}

// ---------------- fp16 mma.sync GEMM + fused epilogue ------------------------
#define GS 40   // smem row stride in halves (32 data + 8 pad = 80B, conflict-free)

template <int EPI>
__global__ __launch_bounds__(256, 2)
void k_gemm_mma(const __half* __restrict__ A,
                const __half* __restrict__ B,
                __half* __restrict__ Ch,
                int K, int NTOT,
                const float* __restrict__ bias,
                const float* __restrict__ gamma,
                const float* __restrict__ beta,
                const float* __restrict__ rm,
                const float* __restrict__ rv) {
    __shared__ __align__(16) __half As[2][128 * GS];
    __shared__ __align__(16) __half Bs[2][128 * GS];

    int tid = threadIdx.x;
    int wid = tid >> 5, lane = tid & 31;
    int warp_m = wid & 1;
    int warp_n = wid >> 1;
    int rowBase = blockIdx.y * 128;
    int colBase = blockIdx.x * 128;

    uint32_t asb = smem_u32(&As[0][0]);
    uint32_t bsb = smem_u32(&Bs[0][0]);
    const uint32_t bufBytes = 128 * GS * 2;

    float acc[4][4][4];
#pragma unroll
    for (int i = 0; i < 4; i++)
#pragma unroll
        for (int j = 0; j < 4; j++)
#pragma unroll
            for (int q = 0; q < 4; q++) acc[i][j][q] = 0.0f;

    const int NC = K >> 5;

    auto load_chunk = [&](int c, int buf) {
        int k0 = c << 5;
#pragma unroll
        for (int t = 0; t < 2; t++) {
            int idx = tid + (t << 8);
            int r = idx >> 2, seg = idx & 3;
            uint32_t doff = (uint32_t)(r * GS + seg * 8) * 2;
            cp_async16(asb + buf * bufBytes + doff,
                       A + (size_t)(rowBase + r) * K + k0 + seg * 8);
            cp_async16(bsb + buf * bufBytes + doff,
                       B + (size_t)(colBase + r) * K + k0 + seg * 8);
        }
        cp_commit();
    };

    load_chunk(0, 0);

    for (int c = 0; c < NC; c++) {
        int buf = c & 1;
        if (c + 1 < NC) {
            load_chunk(c + 1, buf ^ 1);
            cp_wait1();
        } else {
            cp_wait0();
        }
        __syncthreads();

        uint32_t aBase = asb + buf * bufBytes;
        uint32_t bBase = bsb + buf * bufBytes;
#pragma unroll
        for (int kk = 0; kk < 2; kk++) {
            uint32_t af[4][4];
            {
                int row = warp_m * 64 + (lane & 15);
                int kcol = kk * 16 + ((lane >> 4) << 3);
#pragma unroll
                for (int i = 0; i < 4; i++) {
                    uint32_t addr = aBase + (uint32_t)((row + i * 16) * GS + kcol) * 2;
                    ldsm_x4(af[i][0], af[i][1], af[i][2], af[i][3], addr);
                }
            }
            uint32_t bf[4][2];
            {
                int rown = warp_n * 32 + (lane & 7) + ((lane & 16) ? 8 : 0);
                int kcol = kk * 16 + ((lane & 8) ? 8 : 0);
#pragma unroll
                for (int jj = 0; jj < 2; jj++) {
                    uint32_t addr = bBase + (uint32_t)((rown + jj * 16) * GS + kcol) * 2;
                    ldsm_x4(bf[jj * 2][0], bf[jj * 2][1],
                            bf[jj * 2 + 1][0], bf[jj * 2 + 1][1], addr);
                }
            }
#pragma unroll
            for (int i = 0; i < 4; i++)
#pragma unroll
                for (int j = 0; j < 4; j++)
                    mma16816(acc[i][j], af[i], bf[j]);
        }
        __syncthreads();
    }

    int mrow0 = rowBase + warp_m * 64 + (lane >> 2);
    int ncol0 = colBase + warp_n * 32 + ((lane & 3) << 1);
#pragma unroll
    for (int j = 0; j < 4; j++) {
        int n = ncol0 + j * 8;
        float b0 = bias[n], b1 = bias[n + 1];
        float s0 = 0.f, s1 = 0.f, t0 = 0.f, t1 = 0.f, m0 = 0.f, m1 = 0.f;
        if (EPI) {
            s0 = gamma[n]     * rsqrtf(rv[n]     + 1e-5f);
            s1 = gamma[n + 1] * rsqrtf(rv[n + 1] + 1e-5f);
            t0 = beta[n];  t1 = beta[n + 1];
            m0 = rm[n];    m1 = rm[n + 1];
        }
#pragma unroll
        for (int i = 0; i < 4; i++) {
            int m_a = mrow0 + i * 16;
            int m_b = m_a + 8;
            float v0 = acc[i][j][0] + b0, v1 = acc[i][j][1] + b1;
            float v2 = acc[i][j][2] + b0, v3 = acc[i][j][3] + b1;
            if (EPI) {
                v0 = fmaxf((v0 - m0) * s0 + t0, 0.0f);
                v1 = fmaxf((v1 - m1) * s1 + t1, 0.0f);
                v2 = fmaxf((v2 - m0) * s0 + t0, 0.0f);
                v3 = fmaxf((v3 - m1) * s1 + t1, 0.0f);
            }
            if (m_a < N_NODES) {
                uint32_t p = pack_hf2(__float2half_rn(v0), __float2half_rn(v1));
                *(uint32_t*)(Ch + (size_t)m_a * NTOT + n) = p;
            }
            if (m_b < N_NODES) {
                uint32_t p = pack_hf2(__float2half_rn(v2), __float2half_rn(v3));
                *(uint32_t*)(Ch + (size_t)m_b * NTOT + n) = p;
            }
        }
    }
}

// ---------------- pooling: mean + max per graph; segment via binary search --
__global__ void k_pool(const __half* __restrict__ h3,
                       const int* __restrict__ batch,
                       float* __restrict__ out) {
    int g = blockIdx.x;
    int tx = threadIdx.x;
    int lo = 0, hi = N_NODES;
    while (lo < hi) { int mid = (lo + hi) >> 1; if (batch[mid] < g) lo = mid + 1; else hi = mid; }
    int s = lo;
    lo = s; hi = N_NODES;
    while (lo < hi) { int mid = (lo + hi) >> 1; if (batch[mid] < g + 1) lo = mid + 1; else hi = mid; }
    int e = lo;

    float sum[3] = {0.f, 0.f, 0.f};
    float mx[3]  = {-INFINITY, -INFINITY, -INFINITY};
    for (int n = s; n < e; n++) {
#pragma unroll
        for (int c = 0; c < 3; c++) {
            float v = __half2float(h3[(size_t)n * 384 + tx + c * 128]);
            sum[c] += v;
            mx[c] = fmaxf(mx[c], v);
        }
    }
    float inv = 1.0f / fmaxf((float)(e - s), 1.0f);
#pragma unroll
    for (int c = 0; c < 3; c++)
        out[(size_t)g * 384 + tx + c * 128] = sum[c] * inv + mx[c];
}

// ---------------- launch ----------------------------------------------------
extern "C" void kernel_launch(void* const* d_in, const int* in_sizes, int n_in,
                              void* d_out, int out_size) {
    const float* x     = (const float*)d_in[0];
    const int*   ei    = (const int*)d_in[1];   // [2, E] int32
    const int*   src   = ei;
    const int*   dst   = ei + N_EDGES;
    const int*   batch = (const int*)d_in[2];
    const float* W1 = (const float*)d_in[3];
    const float* b1 = (const float*)d_in[4];
    const float* g1 = (const float*)d_in[5];
    const float* be1 = (const float*)d_in[6];
    const float* rm1 = (const float*)d_in[7];
    const float* rv1 = (const float*)d_in[8];
    const float* W2 = (const float*)d_in[9];
    const float* b2 = (const float*)d_in[10];
    const float* g2 = (const float*)d_in[11];
    const float* be2 = (const float*)d_in[12];
    const float* rm2 = (const float*)d_in[13];
    const float* rv2 = (const float*)d_in[14];
    const float* W3 = (const float*)d_in[15];
    const float* b3 = (const float*)d_in[16];
    float* out = (float*)d_out;

    __half *p_xh, *p_bufh, *p_bufh3, *p_Aaug, *p_Baug;
    int *p_deg, *p_rowstart, *p_cursor, *p_bsums;
    cudaGetSymbolAddress((void**)&p_xh, g_xh);
    cudaGetSymbolAddress((void**)&p_bufh, g_bufh);
    cudaGetSymbolAddress((void**)&p_bufh3, g_bufh3);
    cudaGetSymbolAddress((void**)&p_Aaug, g_Aaug);
    cudaGetSymbolAddress((void**)&p_Baug, g_Baug);
    cudaGetSymbolAddress((void**)&p_deg, g_deg);
    cudaGetSymbolAddress((void**)&p_rowstart, g_rowstart);
    cudaGetSymbolAddress((void**)&p_cursor, g_cursor);
    cudaGetSymbolAddress((void**)&p_bsums, g_bsums);

    const int AGG_BLOCKS = (N_NODES + 7) / 8;   // 8 warps/block

    // zeroing via memset node (not counted as kernel launch)
    cudaMemsetAsync(p_deg, 0, N_NODES * sizeof(int));

    // ---- 1..4: CSR construction + x conversion ----
    k_hist<<<(N_EDGES + 255) / 256, 256>>>(dst);
    k_scan_block<<<SCAN_BLOCKS, 1024>>>(p_deg, p_rowstart, N_NODES, p_bsums);
    k_scan_add<<<SCAN_BLOCKS, 1024>>>(p_rowstart, N_NODES, p_bsums,
                                      N_EDGES, p_cursor);
    k_fill_convX<<<(N_NODES * 80 + 255) / 256, 256>>>(src, dst, x, p_xh);

    // ---- 5: layer-1 aggregate ----
    k_agg_pre74h<<<AGG_BLOCKS, 256>>>(p_xh, p_Aaug);
    // ---- 6: all weights -> fp16 ----
    k_convB_all<<<(B_TOTAL + 255) / 256, 256>>>(W1, W2, W3, p_Baug);

    // ---- Layer 1: GEMM K=96 + BN+ReLU -> fp16 h1 ----
    {
        dim3 grid(256 / 128, MPAD / 128);
        k_gemm_mma<1><<<grid, 256>>>(p_Aaug, p_Baug + B1_OFF, p_bufh, 96, 256,
                                     b1, g1, be1, rm1, rv1);
    }
    // ---- Layer 2 ----
    {
        k_agg_pre256h<<<AGG_BLOCKS, 256>>>(p_bufh, p_Aaug);
        dim3 grid(256 / 128, MPAD / 128);
        k_gemm_mma<1><<<grid, 256>>>(p_Aaug, p_Baug + B2_OFF, p_bufh, 256, 256,
                                     b2, g2, be2, rm2, rv2);
    }
    // ---- Layer 3 -> fp16 h3 ----
    {
        k_agg_pre256h<<<AGG_BLOCKS, 256>>>(p_bufh, p_Aaug);
        dim3 grid(384 / 128, MPAD / 128);
        k_gemm_mma<0><<<grid, 256>>>(p_Aaug, p_Baug + B3_OFF, p_bufh3, 256, 384,
                                     b3, (const float*)0, (const float*)0,
                                     (const float*)0, (const float*)0);
    }
    // ---- pooling (segments via binary search on sorted batch) ----
    k_pool<<<N_GRAPHS, 128>>>(p_bufh3, batch, out);
}